// round 17
// baseline (speedup 1.0000x reference)
#include <cuda_runtime.h>

#define BB 2
#define LL 8192
#define HH 16
#define DD 64
#define CC 64
#define NCH 128                     // chunks per (b,h)
#define NBH (BB*HH)                 // 32 scan chains
#define GCH 4                       // chunks per granule (= per warp)
#define NGR (NCH/GCH)               // 32 granules per chain
#define NG  (NBH*NGR)               // 1024 granules
#define YSIZE ((size_t)BB*LL*HH*2*DD)   // 33,554,432
#define PFS 8                       // scan prefetch depth
#define PFR 4                       // replay prefetch depth

// Decoupled-lookback state
__device__ int   g_flag[NG];                 // 0=none, 1=partial, 2=inclusive
__device__ float g_pP[NG * 4];               // partial: granule 2x2 gate
__device__ float g_pZ[(size_t)NG * 128];     // partial: granule carry-from-zero
__device__ float g_iZ[(size_t)NG * 128];     // inclusive: prefix carry AFTER granule

__device__ __forceinline__ float4 f4fma(float s, float4 x, float4 acc) {
    return make_float4(fmaf(s, x.x, acc.x), fmaf(s, x.y, acc.y),
                       fmaf(s, x.z, acc.z), fmaf(s, x.w, acc.w));
}
__device__ __forceinline__ float4 f4scale(float s, float4 x) {
    return make_float4(s * x.x, s * x.y, s * x.z, s * x.w);
}
__device__ __forceinline__ float f4dot(float4 a, float4 b) {
    return a.x*b.x + a.y*b.y + a.z*b.z + a.w*b.w;
}

__global__ void k_reset()
{
    int i = blockIdx.x * blockDim.x + threadIdx.x;
    if (i < NG) g_flag[i] = 0;
}

// ---------------------------------------------------------------------------
// Fused kernel. One warp = one granule = 4 consecutive chunks of one (b,h).
// Ordered granule id W = j*NBH + bh  ->  predecessors have lower blockIdx.
// All 256 blocks are co-resident (<=255 regs, 24KB smem => >=2 blocks/SM),
// so the lookback spin can never deadlock.
// ---------------------------------------------------------------------------
__global__ __launch_bounds__(128) void k_fused(
    const float* __restrict__ Ag, const float* __restrict__ Kg,
    const float* __restrict__ Vg, const float* __restrict__ Bg,
    float* __restrict__ Y, float* __restrict__ cs)
{
    __shared__ float smHF[4][512];   // per warp: 4 chunks' final local h (2x64)
    __shared__ float smAT[4][16];    // per warp: 4 chunks' total 2x2 gate
    __shared__ float smCR[4][512];   // per warp: 4 chunk-start carries (2x64)
    __shared__ float smD [4][512];   // per warp: 4 chunks x 64 steps x (d0,d1)

    int widx = threadIdx.x >> 5;
    int lane = threadIdx.x & 31;
    int W    = blockIdx.x * 4 + widx;    // ordered granule id
    int j    = W >> 5;                   // granule position in chain
    int bh   = W & 31;
    int b    = bh >> 4;
    int h    = bh & 15;
    int grp  = lane >> 3;                // chunk-in-granule
    int g    = lane & 7;
    int c    = j * GCH + grp;
    size_t base = ((size_t)b * LL + (size_t)c * CC) * HH + h;

    // ================= Phase A: local chunk scans =================
    {
        float4 aB[PFS]; float2 vB[PFS]; float bB[PFS]; float4 k0B[PFS], k1B[PFS];
#pragma unroll
        for (int i = 0; i < PFS; i++) {
            size_t idx = base + (size_t)i * HH;
            aB[i]  = __ldg((const float4*)(Ag + idx * 4));
            vB[i]  = __ldg((const float2*)(Vg + idx * 2));
            bB[i]  = __ldg(Bg + idx);
            k0B[i] = __ldg((const float4*)(Kg + idx * 64 + 8 * g));
            k1B[i] = __ldg((const float4*)(Kg + idx * 64 + 8 * g + 4));
        }

        float4 h0[2], h1[2];
#pragma unroll
        for (int i = 0; i < 2; i++) {
            h0[i] = make_float4(0.f, 0.f, 0.f, 0.f);
            h1[i] = make_float4(0.f, 0.f, 0.f, 0.f);
        }
        float p00 = 1.f, p01 = 0.f, p10 = 0.f, p11 = 1.f;

        for (int t = 0; t < CC; t += PFS) {
#pragma unroll
            for (int u = 0; u < PFS; u++) {
                float4 a  = aB[u];
                float2 v  = vB[u];
                float  bt = bB[u];
                float4 k0 = k0B[u], k1 = k1B[u];

                int tn = t + u + PFS;
                if (tn < CC) {
                    size_t idx = base + (size_t)tn * HH;
                    aB[u]  = __ldg((const float4*)(Ag + idx * 4));
                    vB[u]  = __ldg((const float2*)(Vg + idx * 2));
                    bB[u]  = __ldg(Bg + idx);
                    k0B[u] = __ldg((const float4*)(Kg + idx * 64 + 8 * g));
                    k1B[u] = __ldg((const float4*)(Kg + idx * 64 + 8 * g + 4));
                }

                float4 hp0[2], hp1[2];
#pragma unroll
                for (int i = 0; i < 2; i++) {
                    hp0[i] = f4fma(a.y, h1[i], f4scale(a.x, h0[i]));
                    hp1[i] = f4fma(a.w, h1[i], f4scale(a.z, h0[i]));
                }

                float r0 = f4dot(hp0[0], k0) + f4dot(hp0[1], k1);
                float r1 = f4dot(hp1[0], k0) + f4dot(hp1[1], k1);
#pragma unroll
                for (int o = 4; o; o >>= 1) {
                    r0 += __shfl_xor_sync(0xffffffffu, r0, o);
                    r1 += __shfl_xor_sync(0xffffffffu, r1, o);
                }

                float d0 = bt * (v.x - r0);
                float d1 = bt * (v.y - r1);
                h0[0] = f4fma(d0, k0, hp0[0]);  h0[1] = f4fma(d0, k1, hp0[1]);
                h1[0] = f4fma(d1, k0, hp1[0]);  h1[1] = f4fma(d1, k1, hp1[1]);

                float q00 = a.x * p00 + a.y * p10;
                float q01 = a.x * p01 + a.y * p11;
                float q10 = a.z * p00 + a.w * p10;
                float q11 = a.z * p01 + a.w * p11;
                p00 = q00; p01 = q01; p10 = q10; p11 = q11;

                if (g == 0)
                    *(float2*)&smD[widx][grp * 128 + (t + u) * 2] =
                        make_float2(d0, d1);
            }
        }

        // publish chunk results to smem
        float* hf = &smHF[widx][grp * 128];
        ((float4*)hf)[2 * g]          = h0[0];
        ((float4*)hf)[2 * g + 1]      = h0[1];
        ((float4*)hf)[16 + 2 * g]     = h1[0];
        ((float4*)hf)[16 + 2 * g + 1] = h1[1];
        if (g == 0) {
            smAT[widx][grp * 4 + 0] = p00;
            smAT[widx][grp * 4 + 1] = p01;
            smAT[widx][grp * 4 + 2] = p10;
            smAT[widx][grp * 4 + 3] = p11;
        }
    }
    __syncwarp();

    // ============ Phase B: compose granule + decoupled lookback ============
    // lane l owns d = {2l, 2l+1}; z/s held as float2 per row.
    int l = lane;
    float2 z0 = make_float2(0.f, 0.f), z1 = make_float2(0.f, 0.f);
    float P00 = 1.f, P01 = 0.f, P10 = 0.f, P11 = 1.f;
#pragma unroll
    for (int i = 0; i < GCH; i++) {
        const float* hf = &smHF[widx][i * 128];
        float2 hf0 = *(const float2*)(hf + 2 * l);
        float2 hf1 = *(const float2*)(hf + 64 + 2 * l);
        float a00 = smAT[widx][i * 4 + 0], a01 = smAT[widx][i * 4 + 1];
        float a10 = smAT[widx][i * 4 + 2], a11 = smAT[widx][i * 4 + 3];
        float2 n0 = make_float2(fmaf(a00, z0.x, fmaf(a01, z1.x, hf0.x)),
                                fmaf(a00, z0.y, fmaf(a01, z1.y, hf0.y)));
        float2 n1 = make_float2(fmaf(a10, z0.x, fmaf(a11, z1.x, hf1.x)),
                                fmaf(a10, z0.y, fmaf(a11, z1.y, hf1.y)));
        z0 = n0; z1 = n1;
        float t00 = a00 * P00 + a01 * P10, t01 = a00 * P01 + a01 * P11;
        float t10 = a10 * P00 + a11 * P10, t11 = a10 * P01 + a11 * P11;
        P00 = t00; P01 = t01; P10 = t10; P11 = t11;
    }

    size_t zb = (size_t)W * 128;
    float2 s0, s1;                      // carry before this granule
    if (j == 0) {
        // inclusive directly: prefix after granule = z
        *(float2*)(g_iZ + zb + 2 * l)      = z0;
        *(float2*)(g_iZ + zb + 64 + 2 * l) = z1;
        __threadfence();
        if (lane == 0) atomicExch(&g_flag[W], 2);
        s0 = make_float2(0.f, 0.f);
        s1 = make_float2(0.f, 0.f);
    } else {
        // publish partial first (progress guarantee for successors)
        *(float2*)(g_pZ + zb + 2 * l)      = z0;
        *(float2*)(g_pZ + zb + 64 + 2 * l) = z1;
        if (lane == 0) {
            g_pP[W * 4 + 0] = P00; g_pP[W * 4 + 1] = P01;
            g_pP[W * 4 + 2] = P10; g_pP[W * 4 + 3] = P11;
        }
        __threadfence();
        if (lane == 0) atomicExch(&g_flag[W], 1);

        // lookback: G = pending affine covering (p, j)
        float G00 = 1.f, G01 = 0.f, G10 = 0.f, G11 = 1.f;
        float2 Gz0 = make_float2(0.f, 0.f), Gz1 = make_float2(0.f, 0.f);
        int p = W - NBH;
        for (;;) {
            int f;
            if (lane == 0) {
                f = *(volatile int*)(g_flag + p);
                while (f == 0) { __nanosleep(40); f = *(volatile int*)(g_flag + p); }
            }
            f = __shfl_sync(0xffffffffu, f, 0);
            __threadfence();
            if (f == 2) {
                float2 i0 = *(const float2*)(g_iZ + (size_t)p * 128 + 2 * l);
                float2 i1 = *(const float2*)(g_iZ + (size_t)p * 128 + 64 + 2 * l);
                s0 = make_float2(fmaf(G00, i0.x, fmaf(G01, i1.x, Gz0.x)),
                                 fmaf(G00, i0.y, fmaf(G01, i1.y, Gz0.y)));
                s1 = make_float2(fmaf(G10, i0.x, fmaf(G11, i1.x, Gz1.x)),
                                 fmaf(G10, i0.y, fmaf(G11, i1.y, Gz1.y)));
                break;
            } else {
                float q00 = g_pP[p * 4 + 0], q01 = g_pP[p * 4 + 1];
                float q10 = g_pP[p * 4 + 2], q11 = g_pP[p * 4 + 3];
                float2 zp0 = *(const float2*)(g_pZ + (size_t)p * 128 + 2 * l);
                float2 zp1 = *(const float2*)(g_pZ + (size_t)p * 128 + 64 + 2 * l);
                Gz0.x = fmaf(G00, zp0.x, fmaf(G01, zp1.x, Gz0.x));
                Gz0.y = fmaf(G00, zp0.y, fmaf(G01, zp1.y, Gz0.y));
                Gz1.x = fmaf(G10, zp0.x, fmaf(G11, zp1.x, Gz1.x));
                Gz1.y = fmaf(G10, zp0.y, fmaf(G11, zp1.y, Gz1.y));
                float n00 = G00 * q00 + G01 * q10, n01 = G00 * q01 + G01 * q11;
                float n10 = G10 * q00 + G11 * q10, n11 = G10 * q01 + G11 * q11;
                G00 = n00; G01 = n01; G10 = n10; G11 = n11;
                p -= NBH;
            }
        }

        // publish inclusive: prefix after this granule = P*s + z
        float2 e0 = make_float2(fmaf(P00, s0.x, fmaf(P01, s1.x, z0.x)),
                                fmaf(P00, s0.y, fmaf(P01, s1.y, z0.y)));
        float2 e1 = make_float2(fmaf(P10, s0.x, fmaf(P11, s1.x, z1.x)),
                                fmaf(P10, s0.y, fmaf(P11, s1.y, z1.y)));
        *(float2*)(g_iZ + zb + 2 * l)      = e0;
        *(float2*)(g_iZ + zb + 64 + 2 * l) = e1;
        __threadfence();
        if (lane == 0) atomicExch(&g_flag[W], 2);
    }

    // per-chunk carries: cs output + smem for replay
#pragma unroll
    for (int i = 0; i < GCH; i++) {
        size_t w = ((size_t)b * NCH + (size_t)(j * GCH + i)) * HH + h;
        *(float2*)(cs + (w * 2 + 0) * 64 + 2 * l) = s0;
        *(float2*)(cs + (w * 2 + 1) * 64 + 2 * l) = s1;
        float* cr = &smCR[widx][i * 128];
        *(float2*)(cr + 2 * l)      = s0;
        *(float2*)(cr + 64 + 2 * l) = s1;
        const float* hf = &smHF[widx][i * 128];
        float2 hf0 = *(const float2*)(hf + 2 * l);
        float2 hf1 = *(const float2*)(hf + 64 + 2 * l);
        float a00 = smAT[widx][i * 4 + 0], a01 = smAT[widx][i * 4 + 1];
        float a10 = smAT[widx][i * 4 + 2], a11 = smAT[widx][i * 4 + 3];
        float2 n0 = make_float2(fmaf(a00, s0.x, fmaf(a01, s1.x, hf0.x)),
                                fmaf(a00, s0.y, fmaf(a01, s1.y, hf0.y)));
        float2 n1 = make_float2(fmaf(a10, s0.x, fmaf(a11, s1.x, hf1.x)),
                                fmaf(a10, s0.y, fmaf(a11, s1.y, hf1.y)));
        s0 = n0; s1 = n1;
    }
    __syncwarp();

    // ================= Phase C: replay, stream Y =================
    {
        const float* cr = &smCR[widx][grp * 128];
        float4 v00 = ((const float4*)cr)[2 * g];
        float4 v01 = ((const float4*)cr)[2 * g + 1];
        float4 v10 = ((const float4*)cr)[16 + 2 * g];
        float4 v11 = ((const float4*)cr)[16 + 2 * g + 1];

        float4 k0B[PFR], k1B[PFR], aB[PFR]; float2 dB[PFR];
#pragma unroll
        for (int i = 0; i < PFR; i++) {
            size_t idx = base + (size_t)i * HH;
            k0B[i] = __ldg((const float4*)(Kg + idx * 64 + 8 * g));
            k1B[i] = __ldg((const float4*)(Kg + idx * 64 + 8 * g + 4));
            aB[i]  = __ldg((const float4*)(Ag + idx * 4));
            dB[i]  = *(const float2*)&smD[widx][grp * 128 + i * 2];
        }

        for (int t = 0; t < CC; t += PFR) {
#pragma unroll
            for (int u = 0; u < PFR; u++) {
                float4 k0 = k0B[u], k1 = k1B[u], a = aB[u];
                float2 dd = dB[u];

                int tn = t + u + PFR;
                if (tn < CC) {
                    size_t idx = base + (size_t)tn * HH;
                    k0B[u] = __ldg((const float4*)(Kg + idx * 64 + 8 * g));
                    k1B[u] = __ldg((const float4*)(Kg + idx * 64 + 8 * g + 4));
                    aB[u]  = __ldg((const float4*)(Ag + idx * 4));
                    dB[u]  = *(const float2*)&smD[widx][grp * 128 + tn * 2];
                }

                float4 n00 = f4fma(dd.x, k0, f4fma(a.y, v10, f4scale(a.x, v00)));
                float4 n01 = f4fma(dd.x, k1, f4fma(a.y, v11, f4scale(a.x, v01)));
                float4 n10 = f4fma(dd.y, k0, f4fma(a.w, v10, f4scale(a.z, v00)));
                float4 n11 = f4fma(dd.y, k1, f4fma(a.w, v11, f4scale(a.z, v01)));
                v00 = n00; v01 = n01; v10 = n10; v11 = n11;

                size_t idx = base + (size_t)(t + u) * HH;
                float4* yo = (float4*)(Y + idx * 128);
                __stcs(yo + 2 * g,          v00);
                __stcs(yo + 2 * g + 1,      v01);
                __stcs(yo + 16 + 2 * g,     v10);
                __stcs(yo + 16 + 2 * g + 1, v11);
            }
        }
    }
}

extern "C" void kernel_launch(void* const* d_in, const int* in_sizes, int n_in,
                              void* d_out, int out_size)
{
    const float* A    = (const float*)d_in[0];
    const float* K    = (const float*)d_in[1];
    const float* V    = (const float*)d_in[2];
    const float* beta = (const float*)d_in[3];
    float* Y  = (float*)d_out;
    float* cs = Y + YSIZE;   // chunk_states tail of the output buffer

    k_reset<<<4, 256>>>();
    k_fused<<<NG / 4, 128>>>(A, K, V, beta, Y, cs);
}